// round 1
// baseline (speedup 1.0000x reference)
#include <cuda_runtime.h>
#include <cstdint>
#include <cstring>

// ---------------------------------------------------------------------------
// MultiQueryAttention: out = (softmax((x@Wq) Kᵀ / sqrt(d)) V) @ Wo + bo
// B=4, T=2048, H=16, d=128, model=2048.  All fp32, packed f32x2 FMA pipes.
// Stage 1: Q = query@Wq + bq            (SGEMM 8192x2048x2048)
// Stage 2: flash attention per (b,h)    (online softmax, 64x64 tiles)
// Stage 3: out = attn@Wo + bo           (SGEMM 8192x2048x2048)
// ---------------------------------------------------------------------------

#define BATCH 4
#define SEQ   2048
#define NHEAD 16
#define HDIM  128
#define MODEL 2048  // NHEAD*HDIM

// scratch (allocation-free rule: __device__ globals)
__device__ float g_q[(size_t)BATCH * SEQ * MODEL];     // [b,t,h,d] = [8192,2048]
__device__ float g_attn[(size_t)BATCH * SEQ * MODEL];  // [b,t,h,d]

// ---------------- packed f32x2 helpers (Blackwell dual-fp32 pipe) ----------
__device__ __forceinline__ unsigned long long pack2(float lo, float hi) {
    unsigned long long r;
    asm("mov.b64 %0, {%1, %2};" : "=l"(r) : "f"(lo), "f"(hi));
    return r;
}
__device__ __forceinline__ float2 unpack2(unsigned long long v) {
    float2 r;
    asm("mov.b64 {%0, %1}, %2;" : "=f"(r.x), "=f"(r.y) : "l"(v));
    return r;
}
__device__ __forceinline__ void ffma2(unsigned long long& d,
                                      unsigned long long a,
                                      unsigned long long b) {
    asm("fma.rn.f32x2 %0, %1, %2, %0;" : "+l"(d) : "l"(a), "l"(b));
}
__device__ __forceinline__ unsigned long long fmul2(unsigned long long a,
                                                    unsigned long long b) {
    unsigned long long r;
    asm("mul.rn.f32x2 %0, %1, %2;" : "=l"(r) : "l"(a), "l"(b));
    return r;
}

// ---------------------------------------------------------------------------
// SGEMM with bias: C[M,N] = A[M,K] @ B[K,N] + bias[N]
// 128x128 block tile, BK=8, 256 threads, 8x8 per thread, acc packed over j.
// Assumes M%128==0, N%128==0, K%8==0 (true here).
// ---------------------------------------------------------------------------
__global__ __launch_bounds__(256) void sgemm_bias_kernel(
    const float* __restrict__ A, const float* __restrict__ Bm,
    const float* __restrict__ bias, float* __restrict__ C,
    int M, int N, int K)
{
    __shared__ __align__(16) float As[8][128];  // transposed: As[k][row]
    __shared__ __align__(16) float Bs[8][128];  // Bs[k][col]

    const int tid = threadIdx.x;
    const int tx = tid & 15;
    const int ty = tid >> 4;
    const int row0 = blockIdx.y * 128;
    const int col0 = blockIdx.x * 128;

    // load mapping
    const int arow = tid >> 1;            // 0..127
    const int acol = (tid & 1) << 2;      // 0 or 4
    const int brow = tid >> 5;            // 0..7
    const int bcol = (tid & 31) << 2;     // 0..124

    const float* Ap = A + (size_t)(row0 + arow) * K + acol;
    const float* Bp = Bm + (size_t)brow * N + col0 + bcol;

    unsigned long long acc[8][4];
#pragma unroll
    for (int i = 0; i < 8; i++)
#pragma unroll
        for (int j = 0; j < 4; j++) acc[i][j] = 0ull;

    float4 av = *(const float4*)Ap;
    float4 bv = *(const float4*)Bp;

    for (int k0 = 0; k0 < K; k0 += 8) {
        As[acol + 0][arow] = av.x;
        As[acol + 1][arow] = av.y;
        As[acol + 2][arow] = av.z;
        As[acol + 3][arow] = av.w;
        *(float4*)&Bs[brow][bcol] = bv;
        __syncthreads();

        if (k0 + 8 < K) {  // register prefetch of next tile
            av = *(const float4*)(Ap + k0 + 8);
            bv = *(const float4*)(Bp + (size_t)(k0 + 8) * N);
        }

#pragma unroll
        for (int kk = 0; kk < 8; kk++) {
            float a[8];
            *(float4*)(a)     = *(const float4*)&As[kk][ty * 8];
            *(float4*)(a + 4) = *(const float4*)&As[kk][ty * 8 + 4];
            ulonglong2 b01 = *(const ulonglong2*)&Bs[kk][tx * 8];
            ulonglong2 b23 = *(const ulonglong2*)&Bs[kk][tx * 8 + 4];
            unsigned long long bb[4] = {b01.x, b01.y, b23.x, b23.y};
#pragma unroll
            for (int i = 0; i < 8; i++) {
                unsigned long long aa = pack2(a[i], a[i]);
#pragma unroll
                for (int j = 0; j < 4; j++) ffma2(acc[i][j], aa, bb[j]);
            }
        }
        __syncthreads();
    }

#pragma unroll
    for (int i = 0; i < 8; i++) {
        int row = row0 + ty * 8 + i;
#pragma unroll
        for (int j = 0; j < 4; j++) {
            int col = col0 + tx * 8 + j * 2;
            float2 v = unpack2(acc[i][j]);
            v.x += bias[col];
            v.y += bias[col + 1];
            *(float2*)&C[(size_t)row * N + col] = v;
        }
    }
}

// ---------------------------------------------------------------------------
// Flash attention per (b, h): 64 query rows per block, 64-key tiles,
// online softmax. K and V alias one smem buffer (loaded back-to-back).
//   Qs  [64][132]  (row-major, padded for conflict-free k-vector reads)
//   KVs [64][132]  (K tile, then V tile)
//   Ps  [64][80]   (exp'd logits tile; stride 80 => conflict-free STS)
// Thread map: tx=tid&15, ty=tid>>4; rows {ty+16i}, cols {tx+16j} (strided).
// S-GEMM packs the K-reduction in f32x2 pairs (both operands contiguous).
// ---------------------------------------------------------------------------
#define QS_STRIDE 132
#define PS_STRIDE 80
#define ATTN_SMEM ((2 * 64 * QS_STRIDE + 64 * PS_STRIDE) * (int)sizeof(float))

__global__ __launch_bounds__(256) void mqa_attn_kernel(
    const float* __restrict__ qp, const float* __restrict__ kp,
    const float* __restrict__ vp, float* __restrict__ op)
{
    extern __shared__ float sm[];
    float* Qs  = sm;                        // [64][132]
    float* KVs = sm + 64 * QS_STRIDE;       // [64][132]
    float* Ps  = sm + 2 * 64 * QS_STRIDE;   // [64][80]

    const int tid = threadIdx.x;
    const int tx = tid & 15;
    const int ty = tid >> 4;
    const int q0 = blockIdx.x * 64;
    const int h  = blockIdx.y;
    const int b  = blockIdx.z;

    const float* qbase = qp + (((size_t)b * SEQ + q0) * NHEAD + h) * HDIM;
    const float* kbase = kp + (size_t)b * SEQ * HDIM;
    const float* vbase = vp + (size_t)b * SEQ * HDIM;

    // load Q tile [64][128] (row stride in gmem = MODEL)
#pragma unroll
    for (int it = 0; it < 8; it++) {
        int f = tid + 256 * it;
        int r = f >> 5;
        int c = (f & 31) << 2;
        *(float4*)&Qs[r * QS_STRIDE + c] =
            *(const float4*)(qbase + (size_t)r * MODEL + c);
    }

    float mrow[4], lrow[4];
    unsigned long long O2[4][4];  // rows {ty+16i}, col pairs {tx*2+32u, +1}
#pragma unroll
    for (int i = 0; i < 4; i++) {
        mrow[i] = __int_as_float(0xff800000);  // -inf
        lrow[i] = 0.f;
#pragma unroll
        for (int u = 0; u < 4; u++) O2[i][u] = 0ull;
    }
    const float rscale = 0.088388347648318447f;  // 1/sqrt(128)

    for (int kv0 = 0; kv0 < SEQ; kv0 += 64) {
        // ---- load K tile ----
#pragma unroll
        for (int it = 0; it < 8; it++) {
            int f = tid + 256 * it;
            int r = f >> 5;
            int c = (f & 31) << 2;
            *(float4*)&KVs[r * QS_STRIDE + c] =
                *(const float4*)(kbase + (size_t)(kv0 + r) * HDIM + c);
        }
        __syncthreads();

        // ---- S = Q @ K^T (k-pair-packed f32x2 accumulation) ----
        unsigned long long s2[4][4];
#pragma unroll
        for (int i = 0; i < 4; i++)
#pragma unroll
            for (int j = 0; j < 4; j++) s2[i][j] = 0ull;

#pragma unroll
        for (int k0 = 0; k0 < HDIM; k0 += 4) {
            ulonglong2 qv[4], kv[4];
#pragma unroll
            for (int i = 0; i < 4; i++)
                qv[i] = *(const ulonglong2*)&Qs[(ty + 16 * i) * QS_STRIDE + k0];
#pragma unroll
            for (int j = 0; j < 4; j++)
                kv[j] = *(const ulonglong2*)&KVs[(tx + 16 * j) * QS_STRIDE + k0];
#pragma unroll
            for (int i = 0; i < 4; i++)
#pragma unroll
                for (int j = 0; j < 4; j++) {
                    ffma2(s2[i][j], qv[i].x, kv[j].x);
                    ffma2(s2[i][j], qv[i].y, kv[j].y);
                }
        }

        // ---- online softmax (row groups = 16 lanes sharing ty) ----
        float p[4][4];
#pragma unroll
        for (int i = 0; i < 4; i++) {
            float s[4];
#pragma unroll
            for (int j = 0; j < 4; j++) {
                float2 f2 = unpack2(s2[i][j]);
                s[j] = (f2.x + f2.y) * rscale;
            }
            float mx = fmaxf(fmaxf(s[0], s[1]), fmaxf(s[2], s[3]));
#pragma unroll
            for (int d = 8; d >= 1; d >>= 1)
                mx = fmaxf(mx, __shfl_xor_sync(0xffffffffu, mx, d));
            float mnew = fmaxf(mrow[i], mx);
            float fac = __expf(mrow[i] - mnew);
            float rsum = 0.f;
#pragma unroll
            for (int j = 0; j < 4; j++) {
                p[i][j] = __expf(s[j] - mnew);
                rsum += p[i][j];
            }
#pragma unroll
            for (int d = 8; d >= 1; d >>= 1)
                rsum += __shfl_xor_sync(0xffffffffu, rsum, d);
            lrow[i] = lrow[i] * fac + rsum;
            mrow[i] = mnew;
            unsigned long long fac2 = pack2(fac, fac);
#pragma unroll
            for (int u = 0; u < 4; u++) O2[i][u] = fmul2(O2[i][u], fac2);
        }

        // ---- stage P to smem ----
#pragma unroll
        for (int i = 0; i < 4; i++)
#pragma unroll
            for (int j = 0; j < 4; j++)
                Ps[(ty + 16 * i) * PS_STRIDE + tx + 16 * j] = p[i][j];
        __syncthreads();  // K reads done + P visible

        // ---- load V tile into the same buffer ----
#pragma unroll
        for (int it = 0; it < 8; it++) {
            int f = tid + 256 * it;
            int r = f >> 5;
            int c = (f & 31) << 2;
            *(float4*)&KVs[r * QS_STRIDE + c] =
                *(const float4*)(vbase + (size_t)(kv0 + r) * HDIM + c);
        }
        __syncthreads();

        // ---- O += P @ V (output cols packed in f32x2 pairs) ----
#pragma unroll 4
        for (int j = 0; j < 64; j++) {
            unsigned long long vv[4];
#pragma unroll
            for (int u = 0; u < 4; u++)
                vv[u] = *(const unsigned long long*)
                        &KVs[j * QS_STRIDE + tx * 2 + 32 * u];
#pragma unroll
            for (int i = 0; i < 4; i++) {
                float pj = Ps[(ty + 16 * i) * PS_STRIDE + j];
                unsigned long long p2 = pack2(pj, pj);
#pragma unroll
                for (int u = 0; u < 4; u++) ffma2(O2[i][u], p2, vv[u]);
            }
        }
        __syncthreads();  // V/P reads done before next tile overwrites
    }

    // ---- normalize + write attn [b,t,h,d] ----
#pragma unroll
    for (int i = 0; i < 4; i++) {
        float rl = 1.0f / lrow[i];
        int r = q0 + ty + 16 * i;
        float* ob = op + (((size_t)b * SEQ + r) * NHEAD + h) * HDIM;
#pragma unroll
        for (int u = 0; u < 4; u++) {
            float2 o = unpack2(O2[i][u]);
            o.x *= rl;
            o.y *= rl;
            *(float2*)&ob[tx * 2 + 32 * u] = o;
        }
    }
}

// ---------------------------------------------------------------------------
extern "C" void kernel_launch(void* const* d_in, const int* in_sizes, int n_in,
                              void* d_out, int out_size) {
    const float* query = (const float*)d_in[0];
    const float* key   = (const float*)d_in[1];
    const float* value = (const float*)d_in[2];
    const float* Wq    = (const float*)d_in[3];
    const float* bq    = (const float*)d_in[4];
    const float* Wo    = (const float*)d_in[5];
    const float* bo    = (const float*)d_in[6];
    float* out = (float*)d_out;

    float *qproj, *attn;
    cudaGetSymbolAddress((void**)&qproj, g_q);
    cudaGetSymbolAddress((void**)&attn, g_attn);

    const int M = BATCH * SEQ;  // 8192
    dim3 gemm_grid(MODEL / 128, M / 128);

    // Stage 1: Q projection
    sgemm_bias_kernel<<<gemm_grid, 256>>>(query, Wq, bq, qproj, M, MODEL, MODEL);

    // Stage 2: flash attention
    cudaFuncSetAttribute(mqa_attn_kernel,
                         cudaFuncAttributeMaxDynamicSharedMemorySize, ATTN_SMEM);
    dim3 attn_grid(SEQ / 64, NHEAD, BATCH);
    mqa_attn_kernel<<<attn_grid, 256, ATTN_SMEM>>>(qproj, key, value, attn);

    // Stage 3: output projection
    sgemm_bias_kernel<<<gemm_grid, 256>>>(attn, Wo, bo, out, M, MODEL, MODEL);
}